// round 1
// baseline (speedup 1.0000x reference)
#include <cuda_runtime.h>
#include <cuda_bf16.h>

// Problem constants
#define BB   16
#define NN   1024
#define DD   128
#define EE   16384
#define AA   64
#define DIAM 3

// ---------------- device scratch (no allocations allowed) ----------------
__device__ float g_h[BB * NN * DD];          // node state            8 MB
__device__ float g_big[BB * NN * 640];       // [hs|ht|gh] per node  41.9 MB
__device__ float g_agg[BB * NN * DD];        // aggregated messages   8 MB
__device__ float g_gi[BB * NN * 384];        // gi = agg@Wih^T       25 MB
__device__ float g_ef[BB * EE];              // gathered edge scalars 1 MB
__device__ float g_Wbig[128 * 640];          // packed [Ws|Wt|Whh^T]
__device__ float g_bias1[640];               // [0,0,b_hh]
__device__ float g_Wiht[128 * 384];          // W_ih transposed
__device__ int   g_deg[NN];
__device__ int   g_off[NN + 1];
__device__ int   g_eid[EE];                  // CSR: edge ids sorted by tgt (stable)
__device__ int   g_esrc[EE];                 // CSR: src node per slot
__device__ float g_part[BB * 16 * DD];       // pooling partials

__device__ __forceinline__ float selu_f(float x) {
    const float sc = 1.0507009873554805f, al = 1.6732632423543772f;
    return x > 0.f ? sc * x : sc * al * (__expf(x) - 1.f);
}

// ---------------- setup kernels ----------------
__global__ void k_pack(const float* __restrict__ Wmsg, const float* __restrict__ Whh,
                       const float* __restrict__ bhh, const float* __restrict__ Wih) {
    int t = blockIdx.x * blockDim.x + threadIdx.x;
    if (t < 128 * 640) {
        int k = t / 640, c = t % 640;
        float v;
        if (c < 128)       v = Wmsg[k * 128 + c];                 // src part
        else if (c < 256)  v = Wmsg[(128 + k) * 128 + (c - 128)]; // tgt part
        else               v = Whh[(c - 256) * 128 + k];          // W_hh^T
        g_Wbig[k * 640 + c] = v;
    }
    if (t < 640) g_bias1[t] = (t < 256) ? 0.f : bhh[t - 256];
    if (t < 128 * 384) {
        int k = t / 384, j = t % 384;
        g_Wiht[k * 384 + j] = Wih[j * 128 + k];
    }
}

__global__ void k_copyh(const float* __restrict__ nf) {
    int t = blockIdx.x * blockDim.x + threadIdx.x;
    if (t < BB * NN * DD) g_h[t] = nf[t];
}

__global__ void k_ef(const float* __restrict__ edge, const int* __restrict__ src,
                     const int* __restrict__ tgt) {
    int t = blockIdx.x * blockDim.x + threadIdx.x;
    if (t < BB * EE) {
        int b = t / EE, e = t % EE;
        g_ef[t] = edge[(size_t)b * NN * NN + (size_t)src[e] * NN + tgt[e]];
    }
}

// one warp per target node: count incoming edges (stable, no atomics)
__global__ void k_deg(const int* __restrict__ tgt) {
    int n = blockIdx.x, l = threadIdx.x;
    int cnt = 0;
    int e0 = l * (EE / 32);
    for (int e = e0; e < e0 + EE / 32; ++e) cnt += (tgt[e] == n);
    for (int o = 16; o; o >>= 1) cnt += __shfl_down_sync(0xffffffffu, cnt, o);
    if (l == 0) g_deg[n] = cnt;
}

__global__ void k_scan() {  // 1 block, 1024 threads: exclusive scan of g_deg
    __shared__ int s[NN];
    int t = threadIdx.x;
    s[t] = g_deg[t];
    __syncthreads();
    for (int o = 1; o < NN; o <<= 1) {
        int x = (t >= o) ? s[t - o] : 0;
        __syncthreads();
        s[t] += x;
        __syncthreads();
    }
    g_off[t + 1] = s[t];
    if (t == 0) g_off[0] = 0;
}

// stable fill: lane chunks are contiguous in e, so bucket order == ascending e
__global__ void k_fill(const int* __restrict__ tgt, const int* __restrict__ src) {
    int n = blockIdx.x, l = threadIdx.x;
    const int C = EE / 32;
    int cnt = 0;
    int e0 = l * C;
    for (int e = e0; e < e0 + C; ++e) cnt += (tgt[e] == n);
    int ex = cnt;
    for (int o = 1; o < 32; o <<= 1) {
        int x = __shfl_up_sync(0xffffffffu, ex, o);
        if (l >= o) ex += x;
    }
    ex -= cnt;  // exclusive
    int pos = g_off[n] + ex;
    for (int e = e0; e < e0 + C; ++e) {
        if (tgt[e] == n) { g_eid[pos] = e; g_esrc[pos] = src[e]; ++pos; }
    }
}

// ---------------- 128x128x8 fp32 tiled GEMM ----------------
// MODE 0: g_big[16384,640] = g_h[16384,128] @ g_Wbig[128,640] + g_bias1
// MODE 1: g_gi [16384,384] = g_agg[16384,128] @ g_Wiht[128,384] + b_ih
template <int MODE>
__global__ __launch_bounds__(256) void k_gemm(const float* __restrict__ bih) {
    const int Nc = (MODE == 0) ? 640 : 384;
    const float* __restrict__ A    = (MODE == 0) ? g_h    : g_agg;
    const float* __restrict__ Bm   = (MODE == 0) ? g_Wbig : g_Wiht;
    const float* __restrict__ bias = (MODE == 0) ? g_bias1 : bih;
    float* __restrict__ C          = (MODE == 0) ? g_big  : g_gi;

    __shared__ float As[8][132];   // transposed A tile, padded
    __shared__ float Bs[8][128];

    int tid = threadIdx.x;
    int tx = tid & 15, ty = tid >> 4;
    int bm = blockIdx.y, bn = blockIdx.x;

    const float* Ab = A + (size_t)bm * 128 * 128;
    const float* Bb = Bm + bn * 128;

    float acc[8][8];
#pragma unroll
    for (int i = 0; i < 8; ++i)
#pragma unroll
        for (int j = 0; j < 8; ++j) acc[i][j] = 0.f;

    int ar = tid >> 1, ak = (tid & 1) * 4;   // A load: 1 float4 along k
    int br = tid >> 5, bc = (tid & 31) * 4;  // B load: 1 float4 along n

    for (int k0 = 0; k0 < 128; k0 += 8) {
        float4 av = *(const float4*)(Ab + (size_t)ar * 128 + k0 + ak);
        As[ak + 0][ar] = av.x;
        As[ak + 1][ar] = av.y;
        As[ak + 2][ar] = av.z;
        As[ak + 3][ar] = av.w;
        float4 bv = *(const float4*)(Bb + (size_t)(k0 + br) * Nc + bc);
        *(float4*)&Bs[br][bc] = bv;
        __syncthreads();
#pragma unroll
        for (int k = 0; k < 8; ++k) {
            float4 a0 = *(const float4*)&As[k][ty * 8];
            float4 a1 = *(const float4*)&As[k][ty * 8 + 4];
            float4 b0 = *(const float4*)&Bs[k][tx * 8];
            float4 b1 = *(const float4*)&Bs[k][tx * 8 + 4];
            float a[8] = {a0.x, a0.y, a0.z, a0.w, a1.x, a1.y, a1.z, a1.w};
            float b[8] = {b0.x, b0.y, b0.z, b0.w, b1.x, b1.y, b1.z, b1.w};
#pragma unroll
            for (int i = 0; i < 8; ++i)
#pragma unroll
                for (int j = 0; j < 8; ++j) acc[i][j] = fmaf(a[i], b[j], acc[i][j]);
        }
        __syncthreads();
    }

#pragma unroll
    for (int i = 0; i < 8; ++i) {
        int row = bm * 128 + ty * 8 + i;
#pragma unroll
        for (int j = 0; j < 8; ++j) {
            int col = bn * 128 + tx * 8 + j;
            C[(size_t)row * Nc + col] = acc[i][j] + bias[col];
        }
    }
}

// ---------------- fused edge message + deterministic aggregation ----------------
// agg[b,n,d] = sum over incoming edges e (src s):
//   selu( hs[b,s,d] + ht[b,n,d] + ef[b,e]*W_msg[256,d] + b_msg[d] )
__global__ void k_edge(const float* __restrict__ Wmsg, const float* __restrict__ bmsg) {
    int n = blockIdx.x, b = blockIdx.y, d = threadIdx.x;
    float we = Wmsg[256 * 128 + d];
    float bm = bmsg[d];
    const float* bigb = g_big + (size_t)b * NN * 640;
    float htv = bigb[(size_t)n * 640 + 128 + d];
    int s0 = g_off[n], s1 = g_off[n + 1];
    float accv = 0.f;
    for (int s = s0; s < s1; ++s) {
        int e = g_eid[s];
        int sr = g_esrc[s];
        float efv = g_ef[b * EE + e];
        float x = bigb[(size_t)sr * 640 + d] + htv + efv * we + bm;
        accv += selu_f(x);
    }
    g_agg[((size_t)(b * NN + n)) * DD + d] = accv;
}

// ---------------- GRU elementwise ----------------
__global__ void k_gru() {
    int t = blockIdx.x * blockDim.x + threadIdx.x;
    if (t >= BB * NN * DD) return;
    int row = t >> 7, d = t & 127;
    const float* gi = g_gi + (size_t)row * 384;
    const float* gh = g_big + (size_t)row * 640 + 256;
    float ir = gi[d], iz = gi[128 + d], in_ = gi[256 + d];
    float hr = gh[d], hz = gh[128 + d], hn = gh[256 + d];
    float h = g_h[t];
    float r = 1.f / (1.f + __expf(-(ir + hr)));
    float z = 1.f / (1.f + __expf(-(iz + hz)));
    float nv = tanhf(in_ + r * hn);
    g_h[t] = (1.f - z) * nv + z * h;
}

// ---------------- pooling + readout head ----------------
__global__ void k_pool() {  // grid (16 chunks, B), 128 threads
    int c = blockIdx.x, b = blockIdx.y, d = threadIdx.x;
    const float* hb = g_h + ((size_t)b * NN + c * 64) * DD + d;
    float s = 0.f;
#pragma unroll 8
    for (int n = 0; n < 64; ++n) s += hb[(size_t)n * DD];
    g_part[(b * 16 + c) * DD + d] = s;
}

__global__ void k_head(const float* __restrict__ Wr1, const float* __restrict__ br1,
                       const float* __restrict__ Wr2, const float* __restrict__ br2,
                       const float* __restrict__ Wpol, const float* __restrict__ bpol,
                       float* __restrict__ out) {
    int b = blockIdx.x, d = threadIdx.x;  // 128 threads
    __shared__ float p[128], q[128];
    float s = 0.f;
#pragma unroll
    for (int c = 0; c < 16; ++c) s += g_part[(b * 16 + c) * DD + d];
    p[d] = s;
    __syncthreads();
    float y = br1[d];
#pragma unroll 8
    for (int k = 0; k < 128; ++k) y = fmaf(p[k], Wr1[k * 128 + d], y);
    q[d] = selu_f(y);
    __syncthreads();
    y = br2[d];
#pragma unroll 8
    for (int k = 0; k < 128; ++k) y = fmaf(q[k], Wr2[k * 128 + d], y);
    float p2 = selu_f(y);
    __syncthreads();
    p[d] = p2;
    __syncthreads();
    if (d < 64) {
        float o = bpol[d];
#pragma unroll 8
        for (int k = 0; k < 128; ++k) o = fmaf(p[k], Wpol[k * 64 + d], o);
        out[b * 64 + d] = o;
    }
}

// ---------------- launch ----------------
extern "C" void kernel_launch(void* const* d_in, const int* in_sizes, int n_in,
                              void* d_out, int out_size) {
    const float* nf   = (const float*)d_in[0];
    const float* edge = (const float*)d_in[1];
    const int*   src  = (const int*)d_in[2];
    const int*   tgt  = (const int*)d_in[3];
    const float* Wmsg = (const float*)d_in[4];
    const float* bmsg = (const float*)d_in[5];
    const float* Wih  = (const float*)d_in[6];
    const float* Whh  = (const float*)d_in[7];
    const float* bih  = (const float*)d_in[8];
    const float* bhh  = (const float*)d_in[9];
    const float* Wr1  = (const float*)d_in[10];
    const float* br1  = (const float*)d_in[11];
    const float* Wr2  = (const float*)d_in[12];
    const float* br2  = (const float*)d_in[13];
    const float* Wpol = (const float*)d_in[14];
    const float* bpol = (const float*)d_in[15];
    float* out = (float*)d_out;

    k_pack<<<(128 * 640 + 255) / 256, 256>>>(Wmsg, Whh, bhh, Wih);
    k_copyh<<<(BB * NN * DD + 255) / 256, 256>>>(nf);
    k_ef<<<(BB * EE + 255) / 256, 256>>>(edge, src, tgt);
    k_deg<<<NN, 32>>>(tgt);
    k_scan<<<1, NN>>>();
    k_fill<<<NN, 32>>>(tgt, src);

    for (int it = 0; it < DIAM; ++it) {
        k_gemm<0><<<dim3(5, 128), 256>>>(nullptr);
        k_edge<<<dim3(NN, BB), 128>>>(Wmsg, bmsg);
        k_gemm<1><<<dim3(3, 128), 256>>>(bih);
        k_gru<<<(BB * NN * DD + 255) / 256, 256>>>();
    }

    k_pool<<<dim3(16, BB), 128>>>();
    k_head<<<BB, 128>>>(Wr1, br1, Wr2, br2, Wpol, bpol, out);
}

// round 2
// speedup vs baseline: 1.3256x; 1.3256x over previous
#include <cuda_runtime.h>
#include <cuda_bf16.h>

// Problem constants
#define BB   16
#define NN   1024
#define DD   128
#define EE   16384
#define AA   64
#define DIAM 3
#define CH   64           // edge chunks for CSR build
#define CE   (EE / CH)    // 256 edges per chunk

// ---------------- device scratch (no allocations allowed) ----------------
__device__ float g_h[BB * NN * DD];          // node state            8 MB
__device__ float g_big[BB * NN * 640];       // [hs|ht|gh] per node  41.9 MB
__device__ float g_agg[BB * NN * DD];        // aggregated messages   8 MB
__device__ float g_gi[BB * NN * 384];        // gi = agg@Wih^T       25 MB
__device__ float g_ef[BB * EE];              // edge scalars, CSR slot order
__device__ float g_Wbig[128 * 640];          // packed [Ws|Wt|Whh^T]
__device__ float g_bias1[640];               // [0,0,b_hh]
__device__ float g_Wiht[128 * 384];          // W_ih transposed
__device__ int   g_ccnt[CH * NN];            // per-chunk per-node counts -> offsets
__device__ int   g_off[NN + 1];
__device__ int   g_eid[EE];                  // CSR: edge ids sorted by tgt (stable)
__device__ int   g_esrc[EE];                 // CSR: src node per slot
__device__ float g_part[BB * 16 * DD];       // pooling partials

__device__ __forceinline__ float selu_f(float x) {
    const float sc = 1.0507009873554805f, al = 1.6732632423543772f;
    return x > 0.f ? sc * x : sc * al * (__expf(x) - 1.f);
}

// ---------------- setup kernels ----------------
__global__ void k_pack(const float* __restrict__ Wmsg, const float* __restrict__ Whh,
                       const float* __restrict__ bhh, const float* __restrict__ Wih) {
    int t = blockIdx.x * blockDim.x + threadIdx.x;
    if (t < 128 * 640) {
        int k = t / 640, c = t % 640;
        float v;
        if (c < 128)       v = Wmsg[k * 128 + c];                 // src part
        else if (c < 256)  v = Wmsg[(128 + k) * 128 + (c - 128)]; // tgt part
        else               v = Whh[(c - 256) * 128 + k];          // W_hh^T
        g_Wbig[k * 640 + c] = v;
    }
    if (t < 640) g_bias1[t] = (t < 256) ? 0.f : bhh[t - 256];
    if (t < 128 * 384) {
        int k = t / 384, j = t % 384;
        g_Wiht[k * 384 + j] = Wih[j * 128 + k];
    }
}

__global__ void k_copyh(const float* __restrict__ nf) {
    int t = blockIdx.x * blockDim.x + threadIdx.x;
    if (t < BB * NN * DD) g_h[t] = nf[t];
}

// ---- CSR build: chunked histogram (counts deterministic w/ atomics) ----
__global__ void k_cnt(const int* __restrict__ tgt) {  // grid CH, block 256
    __shared__ int c[NN];
    for (int i = threadIdx.x; i < NN; i += 256) c[i] = 0;
    __syncthreads();
    int e = blockIdx.x * CE + threadIdx.x;
    atomicAdd(&c[tgt[e]], 1);
    __syncthreads();
    for (int i = threadIdx.x; i < NN; i += 256) g_ccnt[blockIdx.x * NN + i] = c[i];
}

__global__ void k_scan() {  // 1 block, 1024 threads
    int n = threadIdx.x;
    int run = 0;
    for (int c = 0; c < CH; ++c) {
        int v = g_ccnt[c * NN + n];
        g_ccnt[c * NN + n] = run;  // prefix within node across chunks
        run += v;
    }
    __shared__ int s[NN];
    s[n] = run;
    __syncthreads();
    for (int o = 1; o < NN; o <<= 1) {
        int x = (n >= o) ? s[n - o] : 0;
        __syncthreads();
        s[n] += x;
        __syncthreads();
    }
    int off = s[n] - run;  // exclusive
    g_off[n] = off;
    if (n == NN - 1) g_off[NN] = s[n];
    for (int c = 0; c < CH; ++c) g_ccnt[c * NN + n] += off;
}

// stable fill: one warp per chunk, edges processed in ascending e order
__global__ void k_fill(const int* __restrict__ tgt, const int* __restrict__ src) {
    __shared__ int ctr[NN];
    int lane = threadIdx.x;
    int chunk = blockIdx.x;
    for (int i = lane; i < NN; i += 32) ctr[i] = g_ccnt[chunk * NN + i];
    __syncwarp();
    for (int r = 0; r < CE / 32; ++r) {
        int e = chunk * CE + r * 32 + lane;
        int t = tgt[e];
        unsigned mask = __match_any_sync(0xffffffffu, t);
        int leader = __ffs(mask) - 1;
        int rank = __popc(mask & ((1u << lane) - 1u));
        int base = 0;
        if (lane == leader) { base = ctr[t]; ctr[t] = base + __popc(mask); }
        base = __shfl_sync(0xffffffffu, base, leader);
        g_eid[base + rank] = e;
        g_esrc[base + rank] = src[e];
        __syncwarp();
    }
}

// gather edge scalars directly into CSR slot order (run AFTER k_fill)
__global__ void k_ef(const float* __restrict__ edge, const int* __restrict__ src,
                     const int* __restrict__ tgt) {
    int t = blockIdx.x * blockDim.x + threadIdx.x;
    if (t < BB * EE) {
        int b = t / EE, slot = t % EE;
        int e = g_eid[slot];
        g_ef[t] = edge[(size_t)b * NN * NN + (size_t)src[e] * NN + tgt[e]];
    }
}

// ---------------- double-buffered 128x128x16 fp32 GEMM ----------------
// MODE 0: g_big[16384,640] = g_h[16384,128] @ g_Wbig[128,640] + g_bias1
// MODE 1: g_gi [16384,384] = g_agg[16384,128] @ g_Wiht[128,384] + b_ih
template <int MODE>
__global__ __launch_bounds__(256) void k_gemm(const float* __restrict__ bih) {
    constexpr int Nc = (MODE == 0) ? 640 : 384;
    const float* __restrict__ A    = (MODE == 0) ? g_h    : g_agg;
    const float* __restrict__ Bm   = (MODE == 0) ? g_Wbig : g_Wiht;
    const float* __restrict__ bias = (MODE == 0) ? g_bias1 : bih;
    float* __restrict__ C          = (MODE == 0) ? g_big  : g_gi;

    __shared__ float As[2][16][132];   // [buf][k][row], padded
    __shared__ float Bs[2][16][128];   // [buf][k][col]

    const int tid = threadIdx.x;
    const int bm = blockIdx.y, bn = blockIdx.x;
    const float* Ab = A + (size_t)bm * 128 * 128;
    const float* Bb = Bm + (size_t)bn * 128;

    const int tx = tid & 15, ty = tid >> 4;

    float4 pa[2], pb[2];

    auto fetch = [&](int k0) {
#pragma unroll
        for (int i = 0; i < 2; ++i) {
            int idx = tid * 2 + i;
            int ar = idx >> 2, akq = idx & 3;          // A: row, k-quad
            pa[i] = *(const float4*)(Ab + (size_t)ar * 128 + k0 + akq * 4);
            int br = idx >> 5, bq = idx & 31;          // B: k-row, n-quad
            pb[i] = *(const float4*)(Bb + (size_t)(k0 + br) * Nc + bq * 4);
        }
    };
    auto store = [&](int buf) {
#pragma unroll
        for (int i = 0; i < 2; ++i) {
            int idx = tid * 2 + i;
            int ar = idx >> 2, akq = idx & 3;
            As[buf][akq * 4 + 0][ar] = pa[i].x;
            As[buf][akq * 4 + 1][ar] = pa[i].y;
            As[buf][akq * 4 + 2][ar] = pa[i].z;
            As[buf][akq * 4 + 3][ar] = pa[i].w;
            int br = idx >> 5, bq = idx & 31;
            *(float4*)&Bs[buf][br][bq * 4] = pb[i];
        }
    };

    float acc[8][8];
#pragma unroll
    for (int i = 0; i < 8; ++i)
#pragma unroll
        for (int j = 0; j < 8; ++j) acc[i][j] = 0.f;

    fetch(0);
    store(0);
    __syncthreads();

#pragma unroll
    for (int s = 0; s < 8; ++s) {
        if (s < 7) fetch((s + 1) * 16);
        int buf = s & 1;
#pragma unroll
        for (int k = 0; k < 16; ++k) {
            float4 a0 = *(const float4*)&As[buf][k][ty * 4];
            float4 a1 = *(const float4*)&As[buf][k][64 + ty * 4];
            float4 b0 = *(const float4*)&Bs[buf][k][tx * 4];
            float4 b1 = *(const float4*)&Bs[buf][k][64 + tx * 4];
            float av[8] = {a0.x, a0.y, a0.z, a0.w, a1.x, a1.y, a1.z, a1.w};
            float bv[8] = {b0.x, b0.y, b0.z, b0.w, b1.x, b1.y, b1.z, b1.w};
#pragma unroll
            for (int i = 0; i < 8; ++i)
#pragma unroll
                for (int j = 0; j < 8; ++j) acc[i][j] = fmaf(av[i], bv[j], acc[i][j]);
        }
        if (s < 7) { store(buf ^ 1); __syncthreads(); }
    }

    int c0 = bn * 128 + tx * 4;
    int c1 = c0 + 64;
    float4 bb0 = {bias[c0], bias[c0 + 1], bias[c0 + 2], bias[c0 + 3]};
    float4 bb1 = {bias[c1], bias[c1 + 1], bias[c1 + 2], bias[c1 + 3]};
#pragma unroll
    for (int i = 0; i < 8; ++i) {
        int row = bm * 128 + ((i < 4) ? (ty * 4 + i) : (64 + ty * 4 + i - 4));
        float4 v0 = {acc[i][0] + bb0.x, acc[i][1] + bb0.y, acc[i][2] + bb0.z, acc[i][3] + bb0.w};
        float4 v1 = {acc[i][4] + bb1.x, acc[i][5] + bb1.y, acc[i][6] + bb1.z, acc[i][7] + bb1.w};
        *(float4*)(C + (size_t)row * Nc + c0) = v0;
        *(float4*)(C + (size_t)row * Nc + c1) = v1;
    }
}

// ---------------- fused edge message + deterministic aggregation ----------------
// agg[b,n,d] = sum over CSR slots of node n:
//   selu( hs[b,src,d] + ht[b,n,d] + ef[b,slot]*W_msg[256,d] + b_msg[d] )
__global__ __launch_bounds__(128) void k_edge(const float* __restrict__ Wmsg,
                                              const float* __restrict__ bmsg) {
    int lane = threadIdx.x & 31;          // float4 index over D
    int nl = threadIdx.x >> 5;            // node within block
    int n = blockIdx.x * 4 + nl;
    int b = blockIdx.y;
    float4 we = *(const float4*)(Wmsg + 256 * 128 + lane * 4);
    float4 bm = *(const float4*)(bmsg + lane * 4);
    const float* bigb = g_big + (size_t)b * NN * 640;
    float4 ht = *(const float4*)(bigb + (size_t)n * 640 + 128 + lane * 4);
    const float* efb = g_ef + (size_t)b * EE;
    int s0 = g_off[n], s1 = g_off[n + 1];
    float4 acc = {0.f, 0.f, 0.f, 0.f};
    for (int s = s0; s < s1; ++s) {
        int sr = g_esrc[s];
        float ef = efb[s];
        float4 hs = *(const float4*)(bigb + (size_t)sr * 640 + lane * 4);
        acc.x += selu_f(hs.x + ht.x + ef * we.x + bm.x);
        acc.y += selu_f(hs.y + ht.y + ef * we.y + bm.y);
        acc.z += selu_f(hs.z + ht.z + ef * we.z + bm.z);
        acc.w += selu_f(hs.w + ht.w + ef * we.w + bm.w);
    }
    *(float4*)(g_agg + ((size_t)(b * NN + n)) * DD + lane * 4) = acc;
}

// ---------------- GRU elementwise ----------------
__global__ void k_gru() {
    int t = blockIdx.x * blockDim.x + threadIdx.x;
    if (t >= BB * NN * DD) return;
    int row = t >> 7, d = t & 127;
    const float* gi = g_gi + (size_t)row * 384;
    const float* gh = g_big + (size_t)row * 640 + 256;
    float ir = gi[d], iz = gi[128 + d], in_ = gi[256 + d];
    float hr = gh[d], hz = gh[128 + d], hn = gh[256 + d];
    float h = g_h[t];
    float r = 1.f / (1.f + __expf(-(ir + hr)));
    float z = 1.f / (1.f + __expf(-(iz + hz)));
    float nv = tanhf(in_ + r * hn);
    g_h[t] = (1.f - z) * nv + z * h;
}

// ---------------- pooling + readout head ----------------
__global__ void k_pool() {  // grid (16 chunks, B), 128 threads
    int c = blockIdx.x, b = blockIdx.y, d = threadIdx.x;
    const float* hb = g_h + ((size_t)b * NN + c * 64) * DD + d;
    float s = 0.f;
#pragma unroll 8
    for (int n = 0; n < 64; ++n) s += hb[(size_t)n * DD];
    g_part[(b * 16 + c) * DD + d] = s;
}

__global__ void k_head(const float* __restrict__ Wr1, const float* __restrict__ br1,
                       const float* __restrict__ Wr2, const float* __restrict__ br2,
                       const float* __restrict__ Wpol, const float* __restrict__ bpol,
                       float* __restrict__ out) {
    int b = blockIdx.x, d = threadIdx.x;  // 128 threads
    __shared__ float p[128], q[128];
    float s = 0.f;
#pragma unroll
    for (int c = 0; c < 16; ++c) s += g_part[(b * 16 + c) * DD + d];
    p[d] = s;
    __syncthreads();
    float y = br1[d];
#pragma unroll 8
    for (int k = 0; k < 128; ++k) y = fmaf(p[k], Wr1[k * 128 + d], y);
    q[d] = selu_f(y);
    __syncthreads();
    y = br2[d];
#pragma unroll 8
    for (int k = 0; k < 128; ++k) y = fmaf(q[k], Wr2[k * 128 + d], y);
    float p2 = selu_f(y);
    __syncthreads();
    p[d] = p2;
    __syncthreads();
    if (d < 64) {
        float o = bpol[d];
#pragma unroll 8
        for (int k = 0; k < 128; ++k) o = fmaf(p[k], Wpol[k * 64 + d], o);
        out[b * 64 + d] = o;
    }
}

// ---------------- launch ----------------
extern "C" void kernel_launch(void* const* d_in, const int* in_sizes, int n_in,
                              void* d_out, int out_size) {
    const float* nf   = (const float*)d_in[0];
    const float* edge = (const float*)d_in[1];
    const int*   src  = (const int*)d_in[2];
    const int*   tgt  = (const int*)d_in[3];
    const float* Wmsg = (const float*)d_in[4];
    const float* bmsg = (const float*)d_in[5];
    const float* Wih  = (const float*)d_in[6];
    const float* Whh  = (const float*)d_in[7];
    const float* bih  = (const float*)d_in[8];
    const float* bhh  = (const float*)d_in[9];
    const float* Wr1  = (const float*)d_in[10];
    const float* br1  = (const float*)d_in[11];
    const float* Wr2  = (const float*)d_in[12];
    const float* br2  = (const float*)d_in[13];
    const float* Wpol = (const float*)d_in[14];
    const float* bpol = (const float*)d_in[15];
    float* out = (float*)d_out;

    k_pack<<<(128 * 640 + 255) / 256, 256>>>(Wmsg, Whh, bhh, Wih);
    k_copyh<<<(BB * NN * DD + 255) / 256, 256>>>(nf);
    k_cnt<<<CH, 256>>>(tgt);
    k_scan<<<1, NN>>>();
    k_fill<<<CH, 32>>>(tgt, src);
    k_ef<<<(BB * EE + 255) / 256, 256>>>(edge, src, tgt);

    for (int it = 0; it < DIAM; ++it) {
        k_gemm<0><<<dim3(5, 128), 256>>>(nullptr);
        k_edge<<<dim3(NN / 4, BB), 128>>>(Wmsg, bmsg);
        k_gemm<1><<<dim3(3, 128), 256>>>(bih);
        k_gru<<<(BB * NN * DD + 255) / 256, 256>>>();
    }

    k_pool<<<dim3(16, BB), 128>>>();
    k_head<<<BB, 128>>>(Wr1, br1, Wr2, br2, Wpol, bpol, out);
}